// round 10
// baseline (speedup 1.0000x reference)
#include <cuda_runtime.h>
#include <cuda_bf16.h>
#include <cstdint>
#include <math.h>

#define EMB 1024
#define NH 16
#define HD 64
#define BB 4
#define TT 2048
#define ROWS (BB * TT) /* 8192 */
#define QKC 128        /* quantum-relevant columns (heads 0,1) */

// ---------------- scratch (__device__ globals; no allocation allowed) -------
__device__ float g_qp[ROWS * QKC]; // fp32 x@Wq+bq cols 0..127
__device__ float g_kp[ROWS * QKC]; // fp32 x@Wk+bk cols 0..127

__device__ __nv_bfloat16 g_qh[ROWS * QKC], g_ql[ROWS * QKC]; // quantum(qproj)
__device__ __nv_bfloat16 g_kh[ROWS * QKC], g_kl[ROWS * QKC]; // quantum(kproj)
__device__ __nv_bfloat16 g_vh[ROWS * EMB], g_vl[ROWS * EMB]; // v projection
__device__ __nv_bfloat16 g_aoh[ROWS * QKC], g_aol[ROWS * QKC]; // attn out h0,1

__device__ __nv_bfloat16 g_xh[ROWS * EMB], g_xl[ROWS * EMB];   // x split
__device__ __nv_bfloat16 g_wqh[EMB * EMB], g_wql[EMB * EMB];   // W^T splits
__device__ __nv_bfloat16 g_wkh[EMB * EMB], g_wkl[EMB * EMB];
__device__ __nv_bfloat16 g_wvh[EMB * EMB], g_wvl[EMB * EMB];
__device__ __nv_bfloat16 g_woh[EMB * EMB], g_wol[EMB * EMB];

__device__ float g_pm[BB * 8 * EMB];  // meanV partials
__device__ float g_mv[BB * EMB];      // meanV
__device__ float g_base[BB * EMB];    // per-batch output base (heads 2..15 + bo)

// ---------------- helpers ---------------------------------------------------
__device__ __forceinline__ uint32_t smem_u32(const void* p) {
    uint32_t a;
    asm("{ .reg .u64 t; cvta.to.shared.u64 t, %1; cvt.u32.u64 %0, t; }"
        : "=r"(a) : "l"(p));
    return a;
}

__device__ __forceinline__ void ldsm4(uint32_t* r, uint32_t addr) {
    asm volatile("ldmatrix.sync.aligned.m8n8.x4.shared.b16 {%0,%1,%2,%3}, [%4];"
                 : "=r"(r[0]), "=r"(r[1]), "=r"(r[2]), "=r"(r[3]) : "r"(addr));
}

__device__ __forceinline__ void ldsm4t(uint32_t* r, uint32_t addr) {
    asm volatile(
        "ldmatrix.sync.aligned.m8n8.x4.trans.shared.b16 {%0,%1,%2,%3}, [%4];"
        : "=r"(r[0]), "=r"(r[1]), "=r"(r[2]), "=r"(r[3]) : "r"(addr));
}

__device__ __forceinline__ void mma_bf16(float* d, const uint32_t* a,
                                         uint32_t b0, uint32_t b1) {
    asm("mma.sync.aligned.m16n8k16.row.col.f32.bf16.bf16.f32 "
        "{%0,%1,%2,%3}, {%4,%5,%6,%7}, {%8,%9}, {%0,%1,%2,%3};"
        : "+f"(d[0]), "+f"(d[1]), "+f"(d[2]), "+f"(d[3])
        : "r"(a[0]), "r"(a[1]), "r"(a[2]), "r"(a[3]), "r"(b0), "r"(b1));
}

__device__ __forceinline__ void mma_bf16_4(float* d, uint32_t a0, uint32_t a1,
                                           uint32_t a2, uint32_t a3,
                                           uint32_t b0, uint32_t b1) {
    asm("mma.sync.aligned.m16n8k16.row.col.f32.bf16.bf16.f32 "
        "{%0,%1,%2,%3}, {%4,%5,%6,%7}, {%8,%9}, {%0,%1,%2,%3};"
        : "+f"(d[0]), "+f"(d[1]), "+f"(d[2]), "+f"(d[3])
        : "r"(a0), "r"(a1), "r"(a2), "r"(a3), "r"(b0), "r"(b1));
}

__device__ __forceinline__ void cp16(uint32_t dst, const void* src) {
    asm volatile("cp.async.cg.shared.global [%0], [%1], 16;"
                 :: "r"(dst), "l"(src) : "memory");
}
__device__ __forceinline__ void cp_commit() {
    asm volatile("cp.async.commit_group;" ::: "memory");
}
__device__ __forceinline__ void cp_wait0() {
    asm volatile("cp.async.wait_group 0;" ::: "memory");
}
__device__ __forceinline__ void cp_wait1() {
    asm volatile("cp.async.wait_group 1;" ::: "memory");
}

__device__ __forceinline__ uint32_t packbf2(float a, float b) {
    __nv_bfloat162 t = __halves2bfloat162(__float2bfloat16(a), __float2bfloat16(b));
    return *(uint32_t*)&t;
}

// ---------------------------------------------------------------------------
// split fp32 -> bf16 hi/lo
// ---------------------------------------------------------------------------
__global__ __launch_bounds__(256) void split_bf16(
    const float* __restrict__ src,
    __nv_bfloat16* __restrict__ hi, __nv_bfloat16* __restrict__ lo, int n4)
{
    int i = blockIdx.x * blockDim.x + threadIdx.x;
    if (i >= n4) return;
    float4 v = ((const float4*)src)[i];
    __nv_bfloat16 h0 = __float2bfloat16(v.x), h1 = __float2bfloat16(v.y);
    __nv_bfloat16 h2 = __float2bfloat16(v.z), h3 = __float2bfloat16(v.w);
    __nv_bfloat16 l0 = __float2bfloat16(v.x - __bfloat162float(h0));
    __nv_bfloat16 l1 = __float2bfloat16(v.y - __bfloat162float(h1));
    __nv_bfloat16 l2 = __float2bfloat16(v.z - __bfloat162float(h2));
    __nv_bfloat16 l3 = __float2bfloat16(v.w - __bfloat162float(h3));
    __nv_bfloat162* hp = (__nv_bfloat162*)hi;
    __nv_bfloat162* lp = (__nv_bfloat162*)lo;
    hp[i * 2 + 0] = __halves2bfloat162(h0, h1);
    hp[i * 2 + 1] = __halves2bfloat162(h2, h3);
    lp[i * 2 + 0] = __halves2bfloat162(l0, l1);
    lp[i * 2 + 1] = __halves2bfloat162(l2, l3);
}

// ---------------------------------------------------------------------------
// transpose + split: Wt[n][k] = W[k][n] as bf16 hi/lo
// ---------------------------------------------------------------------------
__global__ __launch_bounds__(256) void tsplit_bf16(
    const float* __restrict__ W,
    __nv_bfloat16* __restrict__ th, __nv_bfloat16* __restrict__ tl)
{
    __shared__ float s[32][33];
    int tx = threadIdx.x, ty = threadIdx.y; // (32, 8)
    int n0 = blockIdx.x * 32, k0 = blockIdx.y * 32;
#pragma unroll
    for (int j = 0; j < 4; j++)
        s[ty + 8 * j][tx] = W[(size_t)(k0 + ty + 8 * j) * EMB + n0 + tx];
    __syncthreads();
#pragma unroll
    for (int j = 0; j < 4; j++) {
        int n = n0 + ty + 8 * j, k = k0 + tx;
        float v = s[tx][ty + 8 * j];
        __nv_bfloat16 h = __float2bfloat16(v);
        th[(size_t)n * EMB + k] = h;
        tl[(size_t)n * EMB + k] = __float2bfloat16(v - __bfloat162float(h));
    }
}

// ---------------------------------------------------------------------------
// GEMM core: cp.async 3-stage pipeline, one barrier per K-chunk.
// Parameterized A/B global row strides and K extent (NC chunks of 32).
// ---------------------------------------------------------------------------
#define SROW 40
#define TILE_B (128 * SROW * 2) /* 10240 */
#define STAGE_B (4 * TILE_B)    /* 40960 */
#define NSTAGE 3
#define GSMEM_TOTAL (NSTAGE * STAGE_B) /* 122880 */

struct GemmCore {
    uint32_t sb;
    int tid;
    uint32_t a_off, b_off;
    const __nv_bfloat16* gsrc[4];
    int gstr[4];
    float acc[4][4][4];

    __device__ __forceinline__ void init(char* smem, int tid_, int wid, int L,
                                         const __nv_bfloat16* ah,
                                         const __nv_bfloat16* al, int astr,
                                         const __nv_bfloat16* bh,
                                         const __nv_bfloat16* bl, int bstr) {
        sb = smem_u32(smem);
        tid = tid_;
        const int warp_m = (wid >> 2) * 64;
        const int warp_n = (wid & 3) * 32;
        a_off = (uint32_t)(warp_m + (L & 15)) * 80 + (L >> 4) * 16;
        b_off = (uint32_t)(warp_n + (L >> 4) * 8 + (L & 7)) * 80 + ((L >> 3) & 1) * 16;
        gsrc[0] = ah; gsrc[1] = al; gsrc[2] = bh; gsrc[3] = bl;
        gstr[0] = astr; gstr[1] = astr; gstr[2] = bstr; gstr[3] = bstr;
#pragma unroll
        for (int mt = 0; mt < 4; mt++)
#pragma unroll
            for (int nt = 0; nt < 4; nt++)
#pragma unroll
                for (int j = 0; j < 4; j++) acc[mt][nt][j] = 0.f;
    }

    __device__ __forceinline__ void issue(int kc, int stg) {
        const int k0 = kc * 32;
        const uint32_t stbase = sb + stg * STAGE_B;
#pragma unroll
        for (int u = 0; u < 8; ++u) {
            const int t = u >> 1;
            const int rem = tid + (u & 1) * 256;
            const int r = rem >> 2, c = rem & 3;
            cp16(stbase + t * TILE_B + (uint32_t)r * 80 + c * 16,
                 gsrc[t] + (size_t)r * gstr[t] + k0 + c * 8);
        }
        cp_commit();
    }

    template <int NC>
    __device__ __forceinline__ void run() {
        issue(0, 0);
        issue(1, 1);
        for (int kc = 0; kc < NC; ++kc) {
            if (kc + 2 < NC) cp_wait1(); else cp_wait0();
            __syncthreads();
            if (kc + 2 < NC) issue(kc + 2, (kc + 2) % NSTAGE);

            const uint32_t st = sb + (kc % NSTAGE) * STAGE_B;
#pragma unroll
            for (int ks = 0; ks < 2; ++ks) {
                uint32_t afh[4][4], afl[4][4], bfh[2][4], bfl[2][4];
#pragma unroll
                for (int mt = 0; mt < 4; mt++) {
                    uint32_t ad = st + a_off + mt * (16 * 80) + ks * 32;
                    ldsm4(afh[mt], ad);
                    ldsm4(afl[mt], ad + TILE_B);
                }
#pragma unroll
                for (int np = 0; np < 2; np++) {
                    uint32_t bd = st + 2 * TILE_B + b_off + np * (16 * 80) + ks * 32;
                    ldsm4(bfh[np], bd);
                    ldsm4(bfl[np], bd + TILE_B);
                }
#pragma unroll
                for (int mt = 0; mt < 4; mt++)
#pragma unroll
                    for (int np = 0; np < 2; np++) {
                        mma_bf16(acc[mt][np * 2 + 0], afh[mt], bfh[np][0], bfh[np][1]);
                        mma_bf16(acc[mt][np * 2 + 1], afh[mt], bfh[np][2], bfh[np][3]);
                    }
#pragma unroll
                for (int mt = 0; mt < 4; mt++)
#pragma unroll
                    for (int np = 0; np < 2; np++) {
                        mma_bf16(acc[mt][np * 2 + 0], afh[mt], bfl[np][0], bfl[np][1]);
                        mma_bf16(acc[mt][np * 2 + 1], afh[mt], bfl[np][2], bfl[np][3]);
                    }
#pragma unroll
                for (int mt = 0; mt < 4; mt++)
#pragma unroll
                    for (int np = 0; np < 2; np++) {
                        mma_bf16(acc[mt][np * 2 + 0], afl[mt], bfh[np][0], bfh[np][1]);
                        mma_bf16(acc[mt][np * 2 + 1], afl[mt], bfh[np][2], bfh[np][3]);
                    }
            }
        }
    }
};

// ---------------------------------------------------------------------------
// Fused projections: grid (10, 64). bx=0: q cols 0..127; bx=1: k cols 0..127;
// bx=2..9: v col-block (bx-2)*128. q,k -> fp32 compact; v -> bf16 hi/lo full.
// ---------------------------------------------------------------------------
__global__ __launch_bounds__(256) void gemm_qkv(
    const __nv_bfloat16* __restrict__ Xh, const __nv_bfloat16* __restrict__ Xl,
    const __nv_bfloat16* __restrict__ Wqh, const __nv_bfloat16* __restrict__ Wql,
    const __nv_bfloat16* __restrict__ Wkh, const __nv_bfloat16* __restrict__ Wkl,
    const __nv_bfloat16* __restrict__ Wvh, const __nv_bfloat16* __restrict__ Wvl,
    const float* __restrict__ bq, const float* __restrict__ bk,
    const float* __restrict__ bv,
    float* __restrict__ Qp, float* __restrict__ Kp,
    __nv_bfloat16* __restrict__ Vh, __nv_bfloat16* __restrict__ Vl)
{
    extern __shared__ char smem[];
    const int tid = threadIdx.x, wid = tid >> 5, L = tid & 31;
    const int bxr = blockIdx.x, by = blockIdx.y;
    const int wsel = (bxr < 2) ? bxr : 2;
    const int bx = (bxr < 2) ? 0 : (bxr - 2);

    const __nv_bfloat16* Bh = (wsel == 0) ? Wqh : (wsel == 1) ? Wkh : Wvh;
    const __nv_bfloat16* Bl = (wsel == 0) ? Wql : (wsel == 1) ? Wkl : Wvl;
    const float* bias = (wsel == 0) ? bq : (wsel == 1) ? bk : bv;

    GemmCore g;
    g.init(smem, tid, wid, L,
           Xh + (size_t)(by * 128) * EMB, Xl + (size_t)(by * 128) * EMB, EMB,
           Bh + (size_t)(bx * 128) * EMB, Bl + (size_t)(bx * 128) * EMB, EMB);
    g.run<EMB / 32>();

    const int warp_m = (wid >> 2) * 64, warp_n = (wid & 3) * 32;
    const int qr = L >> 2, qc = (L & 3) * 2;
#pragma unroll
    for (int mt = 0; mt < 4; mt++) {
#pragma unroll
        for (int nt = 0; nt < 4; nt++) {
            int col = bx * 128 + warp_n + nt * 8 + qc;
            float b0 = bias[col], b1 = bias[col + 1];
            int r0 = by * 128 + warp_m + mt * 16 + qr;
            float v00 = g.acc[mt][nt][0] + b0, v01 = g.acc[mt][nt][1] + b1;
            float v10 = g.acc[mt][nt][2] + b0, v11 = g.acc[mt][nt][3] + b1;
            if (wsel < 2) {
                float* dst = (wsel == 0) ? Qp : Kp;
                *(float2*)&dst[(size_t)r0 * QKC + col] = make_float2(v00, v01);
                *(float2*)&dst[(size_t)(r0 + 8) * QKC + col] = make_float2(v10, v11);
            } else {
                float r00 = v00 - __bfloat162float(__float2bfloat16(v00));
                float r01 = v01 - __bfloat162float(__float2bfloat16(v01));
                float r10 = v10 - __bfloat162float(__float2bfloat16(v10));
                float r11 = v11 - __bfloat162float(__float2bfloat16(v11));
                *(uint32_t*)&Vh[(size_t)r0 * EMB + col] = packbf2(v00, v01);
                *(uint32_t*)&Vh[(size_t)(r0 + 8) * EMB + col] = packbf2(v10, v11);
                *(uint32_t*)&Vl[(size_t)r0 * EMB + col] = packbf2(r00, r01);
                *(uint32_t*)&Vl[(size_t)(r0 + 8) * EMB + col] = packbf2(r10, r11);
            }
        }
    }
}

// ---------------------------------------------------------------------------
// quantum: cumprod(cos) over 128 dims, warp per row. Fused q+k.
// ---------------------------------------------------------------------------
__global__ __launch_bounds__(256) void quantum_scan128(
    const float* __restrict__ inq, const float* __restrict__ ink,
    __nv_bfloat16* __restrict__ qh, __nv_bfloat16* __restrict__ ql,
    __nv_bfloat16* __restrict__ kh, __nv_bfloat16* __restrict__ kl)
{
    int gw = blockIdx.x * 8 + (threadIdx.x >> 5);
    int lane = threadIdx.x & 31;
    int row = (gw < ROWS) ? gw : gw - ROWS;
    const float* in = (gw < ROWS) ? inq : ink;
    __nv_bfloat16* oh = (gw < ROWS) ? qh : kh;
    __nv_bfloat16* ol = (gw < ROWS) ? ql : kl;

    float4 v = ((const float4*)(in + (size_t)row * QKC))[lane];
    float c0 = cosf(v.x), c1 = cosf(v.y), c2 = cosf(v.z), c3 = cosf(v.w);
    float p0 = c0, p1 = p0 * c1, p2 = p1 * c2, p3 = p2 * c3;

    float t = p3;
#pragma unroll
    for (int off = 1; off < 32; off <<= 1) {
        float o = __shfl_up_sync(0xffffffffu, t, off);
        if (lane >= off) t *= o;
    }
    float pref = __shfl_up_sync(0xffffffffu, t, 1);
    if (lane == 0) pref = 1.f;

    float f0 = pref * p0, f1 = pref * p1, f2 = pref * p2, f3 = pref * p3;
    uint32_t* hp = (uint32_t*)(oh + (size_t)row * QKC);
    uint32_t* lp = (uint32_t*)(ol + (size_t)row * QKC);
    hp[lane * 2 + 0] = packbf2(f0, f1);
    hp[lane * 2 + 1] = packbf2(f2, f3);
    float r0 = f0 - __bfloat162float(__float2bfloat16(f0));
    float r1 = f1 - __bfloat162float(__float2bfloat16(f1));
    float r2 = f2 - __bfloat162float(__float2bfloat16(f2));
    float r3 = f3 - __bfloat162float(__float2bfloat16(f3));
    lp[lane * 2 + 0] = packbf2(r0, r1);
    lp[lane * 2 + 1] = packbf2(r2, r3);
}

// ---------------------------------------------------------------------------
// Tensor-core flash attention (heads 0,1 only). Q/K compact stride 128, V EMB.
// ---------------------------------------------------------------------------
#define FSTRIDE 144
#define FQ_B (128 * FSTRIDE)
#define FKV_B (64 * FSTRIDE)
#define FSTAGE_B (4 * FKV_B)
#define FSMEM_TOTAL (2 * FQ_B + 2 * FSTAGE_B) /* 110592 */

__global__ __launch_bounds__(256) void flash_tc(
    const __nv_bfloat16* __restrict__ Qh_g, const __nv_bfloat16* __restrict__ Ql_g,
    const __nv_bfloat16* __restrict__ Kh_g, const __nv_bfloat16* __restrict__ Kl_g,
    const __nv_bfloat16* __restrict__ Vh_g, const __nv_bfloat16* __restrict__ Vl_g,
    __nv_bfloat16* __restrict__ Oh, __nv_bfloat16* __restrict__ Ol)
{
    extern __shared__ char smem[];
    const int tid = threadIdx.x, wid = tid >> 5, L = tid & 31;
    const int bh = blockIdx.y;
    const int b = bh >> 1, h = bh & 1;
    const int q0 = blockIdx.x * 128;
    const size_t rb = (size_t)b * TT;
    const int cb = h * HD;
    const uint32_t sb = smem_u32(smem);

#pragma unroll
    for (int u = 0; u < 4; ++u) {
        int idx = tid + u * 256;
        int r = idx >> 3, c = idx & 7;
        const size_t go = (rb + q0 + r) * QKC + cb + c * 8;
        *(uint4*)(smem + r * FSTRIDE + c * 16) = *(const uint4*)(Qh_g + go);
        *(uint4*)(smem + FQ_B + r * FSTRIDE + c * 16) = *(const uint4*)(Ql_g + go);
    }

    const __nv_bfloat16* kvsrc[4] = {Kh_g, Kl_g, Vh_g, Vl_g};
    auto issue_kv = [&](int key0, int stg) {
#pragma unroll
        for (int u = 0; u < 8; ++u) {
            int idx = tid + u * 256;
            int t = idx >> 9, rem = idx & 511;
            int r = rem >> 3, c = rem & 7;
            int str = (t < 2) ? QKC : EMB;
            uint32_t dst = sb + 2 * FQ_B + stg * FSTAGE_B + t * FKV_B +
                           r * FSTRIDE + c * 16;
            cp16(dst, kvsrc[t] + (rb + key0 + r) * (size_t)str + cb + c * 8);
        }
        cp_commit();
    };

    issue_kv(0, 0);
    __syncthreads();

    const uint32_t qa_off = (uint32_t)(wid * 16 + (L & 15)) * FSTRIDE + (L >> 4) * 16;
    uint32_t qfh[4][4], qfl[4][4];
#pragma unroll
    for (int kk = 0; kk < 4; ++kk) {
        ldsm4(qfh[kk], sb + qa_off + kk * 32);
        ldsm4(qfl[kk], sb + FQ_B + qa_off + kk * 32);
    }

    const uint32_t kb_off =
        (uint32_t)((L >> 4) * 8 + (L & 7)) * FSTRIDE + ((L >> 3) & 1) * 16;
    const uint32_t vt_key = ((L >> 3) & 1) * 8 + (L & 7);
    const uint32_t vt_d = (L >> 4) * 8;

    float mA = -INFINITY, mB = -INFINITY, lA = 0.f, lB = 0.f;
    float oacc[8][4];
#pragma unroll
    for (int nt = 0; nt < 8; nt++)
#pragma unroll
        for (int j = 0; j < 4; j++) oacc[nt][j] = 0.f;

    const int NT = TT / 64;
    for (int kt = 0; kt < NT; ++kt) {
        const int cur = kt & 1;
        cp_wait0();
        __syncthreads();
        if (kt + 1 < NT) issue_kv((kt + 1) * 64, cur ^ 1);

        const uint32_t Kh_s = sb + 2 * FQ_B + cur * FSTAGE_B;
        const uint32_t Kl_s = Kh_s + FKV_B;
        const uint32_t Vh_s = Kh_s + 2 * FKV_B;
        const uint32_t Vl_s = Kh_s + 3 * FKV_B;

        float sacc[8][4];
#pragma unroll
        for (int nt = 0; nt < 8; nt++)
#pragma unroll
            for (int j = 0; j < 4; j++) sacc[nt][j] = 0.f;

#pragma unroll
        for (int kk = 0; kk < 4; ++kk) {
            uint32_t kh[4][4], kl[4][4];
#pragma unroll
            for (int np = 0; np < 4; np++) {
                uint32_t bd = kb_off + np * (16 * FSTRIDE) + kk * 32;
                ldsm4(kh[np], Kh_s + bd);
                ldsm4(kl[np], Kl_s + bd);
            }
#pragma unroll
            for (int np = 0; np < 4; np++) {
                mma_bf16(sacc[np * 2 + 0], qfh[kk], kh[np][0], kh[np][1]);
                mma_bf16(sacc[np * 2 + 1], qfh[kk], kh[np][2], kh[np][3]);
            }
#pragma unroll
            for (int np = 0; np < 4; np++) {
                mma_bf16(sacc[np * 2 + 0], qfh[kk], kl[np][0], kl[np][1]);
                mma_bf16(sacc[np * 2 + 1], qfh[kk], kl[np][2], kl[np][3]);
            }
#pragma unroll
            for (int np = 0; np < 4; np++) {
                mma_bf16(sacc[np * 2 + 0], qfl[kk], kh[np][0], kh[np][1]);
                mma_bf16(sacc[np * 2 + 1], qfl[kk], kh[np][2], kh[np][3]);
            }
        }

        float mxA = -INFINITY, mxB = -INFINITY;
#pragma unroll
        for (int nt = 0; nt < 8; nt++) {
            sacc[nt][0] *= 0.125f; sacc[nt][1] *= 0.125f;
            sacc[nt][2] *= 0.125f; sacc[nt][3] *= 0.125f;
            mxA = fmaxf(mxA, fmaxf(sacc[nt][0], sacc[nt][1]));
            mxB = fmaxf(mxB, fmaxf(sacc[nt][2], sacc[nt][3]));
        }
        mxA = fmaxf(mxA, __shfl_xor_sync(0xffffffffu, mxA, 1));
        mxA = fmaxf(mxA, __shfl_xor_sync(0xffffffffu, mxA, 2));
        mxB = fmaxf(mxB, __shfl_xor_sync(0xffffffffu, mxB, 1));
        mxB = fmaxf(mxB, __shfl_xor_sync(0xffffffffu, mxB, 2));

        float mnA = fmaxf(mA, mxA), mnB = fmaxf(mB, mxB);
        float corrA = __expf(mA - mnA), corrB = __expf(mB - mnB);

        uint32_t ph01[8], ph23[8], pl01[8], pl23[8];
        float sumA = 0.f, sumB = 0.f;
#pragma unroll
        for (int nt = 0; nt < 8; nt++) {
            float p0 = __expf(sacc[nt][0] - mnA);
            float p1 = __expf(sacc[nt][1] - mnA);
            float p2 = __expf(sacc[nt][2] - mnB);
            float p3 = __expf(sacc[nt][3] - mnB);
            sumA += p0 + p1;
            sumB += p2 + p3;
            ph01[nt] = packbf2(p0, p1);
            ph23[nt] = packbf2(p2, p3);
            float r0 = p0 - __bfloat162float(__float2bfloat16(p0));
            float r1 = p1 - __bfloat162float(__float2bfloat16(p1));
            float r2 = p2 - __bfloat162float(__float2bfloat16(p2));
            float r3 = p3 - __bfloat162float(__float2bfloat16(p3));
            pl01[nt] = packbf2(r0, r1);
            pl23[nt] = packbf2(r2, r3);
        }
        sumA += __shfl_xor_sync(0xffffffffu, sumA, 1);
        sumA += __shfl_xor_sync(0xffffffffu, sumA, 2);
        sumB += __shfl_xor_sync(0xffffffffu, sumB, 1);
        sumB += __shfl_xor_sync(0xffffffffu, sumB, 2);

        lA = lA * corrA + sumA; mA = mnA;
        lB = lB * corrB + sumB; mB = mnB;
#pragma unroll
        for (int nt = 0; nt < 8; nt++) {
            oacc[nt][0] *= corrA; oacc[nt][1] *= corrA;
            oacc[nt][2] *= corrB; oacc[nt][3] *= corrB;
        }

#pragma unroll
        for (int kk = 0; kk < 4; ++kk) {
            uint32_t vkey = (vt_key + kk * 16) * FSTRIDE;
#pragma unroll
            for (int pr = 0; pr < 2; ++pr) {
                uint32_t vh[2][4], vl[2][4];
#pragma unroll
                for (int j = 0; j < 2; ++j) {
                    uint32_t va = vkey + (vt_d + (pr * 2 + j) * 16) * 2;
                    ldsm4t(vh[j], Vh_s + va);
                    ldsm4t(vl[j], Vl_s + va);
                }
#pragma unroll
                for (int j = 0; j < 2; ++j) {
                    int p = pr * 2 + j;
                    mma_bf16_4(oacc[2 * p + 0], ph01[2 * kk], ph23[2 * kk],
                               ph01[2 * kk + 1], ph23[2 * kk + 1], vh[j][0], vh[j][1]);
                    mma_bf16_4(oacc[2 * p + 1], ph01[2 * kk], ph23[2 * kk],
                               ph01[2 * kk + 1], ph23[2 * kk + 1], vh[j][2], vh[j][3]);
                }
#pragma unroll
                for (int j = 0; j < 2; ++j) {
                    int p = pr * 2 + j;
                    mma_bf16_4(oacc[2 * p + 0], ph01[2 * kk], ph23[2 * kk],
                               ph01[2 * kk + 1], ph23[2 * kk + 1], vl[j][0], vl[j][1]);
                    mma_bf16_4(oacc[2 * p + 1], ph01[2 * kk], ph23[2 * kk],
                               ph01[2 * kk + 1], ph23[2 * kk + 1], vl[j][2], vl[j][3]);
                }
#pragma unroll
                for (int j = 0; j < 2; ++j) {
                    int p = pr * 2 + j;
                    mma_bf16_4(oacc[2 * p + 0], pl01[2 * kk], pl23[2 * kk],
                               pl01[2 * kk + 1], pl23[2 * kk + 1], vh[j][0], vh[j][1]);
                    mma_bf16_4(oacc[2 * p + 1], pl01[2 * kk], pl23[2 * kk],
                               pl01[2 * kk + 1], pl23[2 * kk + 1], vh[j][2], vh[j][3]);
                }
            }
        }
    }

    float invA = 1.0f / lA, invB = 1.0f / lB;
    const size_t rowA = (rb + q0 + wid * 16 + (L >> 2)) * QKC;
    const size_t rowB = rowA + 8 * QKC;
#pragma unroll
    for (int nt = 0; nt < 8; nt++) {
        int col = cb + nt * 8 + (L & 3) * 2;
        float v0 = oacc[nt][0] * invA, v1 = oacc[nt][1] * invA;
        float v2 = oacc[nt][2] * invB, v3 = oacc[nt][3] * invB;
        *(uint32_t*)&Oh[rowA + col] = packbf2(v0, v1);
        *(uint32_t*)&Oh[rowB + col] = packbf2(v2, v3);
        float r0 = v0 - __bfloat162float(__float2bfloat16(v0));
        float r1 = v1 - __bfloat162float(__float2bfloat16(v1));
        float r2 = v2 - __bfloat162float(__float2bfloat16(v2));
        float r3 = v3 - __bfloat162float(__float2bfloat16(v3));
        *(uint32_t*)&Ol[rowA + col] = packbf2(r0, r1);
        *(uint32_t*)&Ol[rowB + col] = packbf2(r2, r3);
    }
}

// ---------------------------------------------------------------------------
// meanV partial sums over 256-row chunks, cols 128..1023.
// ---------------------------------------------------------------------------
__global__ __launch_bounds__(256) void meanv_part(
    const __nv_bfloat16* __restrict__ Vh, const __nv_bfloat16* __restrict__ Vl,
    float* __restrict__ pm)
{
    __shared__ float sm[256];
    int tid = threadIdx.x;
    int col = 128 + blockIdx.x * 64 + (tid & 63);
    int sub = tid >> 6;
    int b = blockIdx.y, chunk = blockIdx.z;
    int row0 = b * TT + chunk * 256 + sub * 64;
    float s = 0.f;
    for (int r = 0; r < 64; ++r) {
        size_t idx = (size_t)(row0 + r) * EMB + col;
        s += __bfloat162float(Vh[idx]) + __bfloat162float(Vl[idx]);
    }
    sm[tid] = s;
    __syncthreads();
    if (sub == 0)
        pm[((size_t)b * 8 + chunk) * EMB + col] =
            sm[tid] + sm[tid + 64] + sm[tid + 128] + sm[tid + 192];
}

__global__ __launch_bounds__(128) void meanv_reduce(const float* __restrict__ pm,
                                                    float* __restrict__ mv)
{
    int col = 128 + blockIdx.x * 128 + threadIdx.x;
    int b = blockIdx.y;
    float s = 0.f;
#pragma unroll
    for (int c = 0; c < 8; ++c) s += pm[((size_t)b * 8 + c) * EMB + col];
    mv[(size_t)b * EMB + col] = s * (1.f / TT);
}

// base[b][n] = bo[n] + sum_{c=128..1023} mv[b][c] * Wo[c][n]
__global__ __launch_bounds__(256) void base_out(
    const float* __restrict__ mv,
    const __nv_bfloat16* __restrict__ WoTh, const __nv_bfloat16* __restrict__ WoTl,
    const float* __restrict__ bo, float* __restrict__ base)
{
    int n = blockIdx.x * 256 + threadIdx.x;
    int b = blockIdx.y;
    float acc = bo[n];
    const __nv_bfloat16* rh = WoTh + (size_t)n * EMB;
    const __nv_bfloat16* rl = WoTl + (size_t)n * EMB;
    const float* m = mv + (size_t)b * EMB;
    for (int c = 128; c < EMB; ++c)
        acc += m[c] * (__bfloat162float(rh[c]) + __bfloat162float(rl[c]));
    base[(size_t)b * EMB + n] = acc;
}

// ---------------------------------------------------------------------------
// Output projection, K=128 (heads 0,1 contribution) + per-batch base.
// ---------------------------------------------------------------------------
__global__ __launch_bounds__(256) void gemm_out128(
    const __nv_bfloat16* __restrict__ Ah, const __nv_bfloat16* __restrict__ Al,
    const __nv_bfloat16* __restrict__ Bh, const __nv_bfloat16* __restrict__ Bl,
    const float* __restrict__ base, float* __restrict__ C)
{
    extern __shared__ char smem[];
    const int tid = threadIdx.x, wid = tid >> 5, L = tid & 31;
    const int bx = blockIdx.x, by = blockIdx.y;

    GemmCore g;
    g.init(smem, tid, wid, L,
           Ah + (size_t)(by * 128) * QKC, Al + (size_t)(by * 128) * QKC, QKC,
           Bh + (size_t)(bx * 128) * EMB, Bl + (size_t)(bx * 128) * EMB, EMB);
    g.run<QKC / 32>();

    const int b = by >> 4; // 16 row-blocks per batch
    const int warp_m = (wid >> 2) * 64, warp_n = (wid & 3) * 32;
    const int qr = L >> 2, qc = (L & 3) * 2;
#pragma unroll
    for (int mt = 0; mt < 4; mt++) {
#pragma unroll
        for (int nt = 0; nt < 4; nt++) {
            int col = bx * 128 + warp_n + nt * 8 + qc;
            float b0 = base[(size_t)b * EMB + col];
            float b1 = base[(size_t)b * EMB + col + 1];
            int r0 = by * 128 + warp_m + mt * 16 + qr;
            *(float2*)&C[(size_t)r0 * EMB + col] =
                make_float2(g.acc[mt][nt][0] + b0, g.acc[mt][nt][1] + b1);
            *(float2*)&C[(size_t)(r0 + 8) * EMB + col] =
                make_float2(g.acc[mt][nt][2] + b0, g.acc[mt][nt][3] + b1);
        }
    }
}

// ---------------------------------------------------------------------------
extern "C" void kernel_launch(void* const* d_in, const int* in_sizes, int n_in,
                              void* d_out, int out_size)
{
    const float* x  = (const float*)d_in[0];
    const float* Wq = (const float*)d_in[1];
    const float* bq = (const float*)d_in[2];
    const float* Wk = (const float*)d_in[3];
    const float* bk = (const float*)d_in[4];
    const float* Wv = (const float*)d_in[5];
    const float* bv = (const float*)d_in[6];
    const float* Wo = (const float*)d_in[7];
    const float* bo = (const float*)d_in[8];
    float* out = (float*)d_out;

    float *qp, *kp, *pm, *mv, *base;
    cudaGetSymbolAddress((void**)&qp, g_qp);
    cudaGetSymbolAddress((void**)&kp, g_kp);
    cudaGetSymbolAddress((void**)&pm, g_pm);
    cudaGetSymbolAddress((void**)&mv, g_mv);
    cudaGetSymbolAddress((void**)&base, g_base);

    __nv_bfloat16 *qh, *ql, *kh, *kl, *vh, *vl, *aoh, *aol, *xh, *xl;
    __nv_bfloat16 *wqh, *wql, *wkh, *wkl, *wvh, *wvl, *woh, *wol;
    cudaGetSymbolAddress((void**)&qh, g_qh);
    cudaGetSymbolAddress((void**)&ql, g_ql);
    cudaGetSymbolAddress((void**)&kh, g_kh);
    cudaGetSymbolAddress((void**)&kl, g_kl);
    cudaGetSymbolAddress((void**)&vh, g_vh);
    cudaGetSymbolAddress((void**)&vl, g_vl);
    cudaGetSymbolAddress((void**)&aoh, g_aoh);
    cudaGetSymbolAddress((void**)&aol, g_aol);
    cudaGetSymbolAddress((void**)&xh, g_xh);
    cudaGetSymbolAddress((void**)&xl, g_xl);
    cudaGetSymbolAddress((void**)&wqh, g_wqh);
    cudaGetSymbolAddress((void**)&wql, g_wql);
    cudaGetSymbolAddress((void**)&wkh, g_wkh);
    cudaGetSymbolAddress((void**)&wkl, g_wkl);
    cudaGetSymbolAddress((void**)&wvh, g_wvh);
    cudaGetSymbolAddress((void**)&wvl, g_wvl);
    cudaGetSymbolAddress((void**)&woh, g_woh);
    cudaGetSymbolAddress((void**)&wol, g_wol);

    cudaFuncSetAttribute(gemm_qkv, cudaFuncAttributeMaxDynamicSharedMemorySize,
                         GSMEM_TOTAL);
    cudaFuncSetAttribute(gemm_out128, cudaFuncAttributeMaxDynamicSharedMemorySize,
                         GSMEM_TOTAL);
    cudaFuncSetAttribute(flash_tc, cudaFuncAttributeMaxDynamicSharedMemorySize,
                         FSMEM_TOTAL);

    const int n4 = ROWS * EMB / 4;
    split_bf16<<<(n4 + 255) / 256, 256>>>(x, xh, xl, n4);

    dim3 tb(32, 8);
    tsplit_bf16<<<dim3(4, 32), tb>>>(Wq, wqh, wql);   // only rows n<128 needed
    tsplit_bf16<<<dim3(4, 32), tb>>>(Wk, wkh, wkl);   // only rows n<128 needed
    tsplit_bf16<<<dim3(32, 32), tb>>>(Wv, wvh, wvl);
    tsplit_bf16<<<dim3(32, 32), tb>>>(Wo, woh, wol);

    gemm_qkv<<<dim3(10, ROWS / 128), 256, GSMEM_TOTAL>>>(
        xh, xl, wqh, wql, wkh, wkl, wvh, wvl, bq, bk, bv, qp, kp, vh, vl);

    quantum_scan128<<<2 * ROWS / 8, 256>>>(qp, kp, qh, ql, kh, kl);

    // Role swap per reference: query = quantum(k-proj), key = quantum(q-proj)
    flash_tc<<<dim3(TT / 128, BB * 2), 256, FSMEM_TOTAL>>>(
        kh, kl, qh, ql, vh, vl, aoh, aol);

    meanv_part<<<dim3(14, BB, 8), 256>>>(vh, vl, pm);
    meanv_reduce<<<dim3(7, BB), 128>>>(pm, mv);
    base_out<<<dim3(EMB / 256, BB), 256>>>(mv, woh, wol, bo, base);

    gemm_out128<<<dim3(EMB / 128, ROWS / 128), 256, GSMEM_TOTAL>>>(
        aoh, aol, woh, wol, base, out);
}

// round 15
// speedup vs baseline: 1.6442x; 1.6442x over previous
#include <cuda_runtime.h>
#include <cuda_bf16.h>
#include <cstdint>
#include <math.h>

#define EMB 1024
#define NH 16
#define HD 64
#define BB 4
#define TT 2048
#define ROWS (BB * TT) /* 8192 */
#define QKC 128        /* quantum-relevant columns (heads 0,1) */

// ---------------- scratch (__device__ globals; no allocation allowed) -------
__device__ float g_qp[ROWS * QKC]; // fp32 x@Wq+bq cols 0..127
__device__ float g_kp[ROWS * QKC]; // fp32 x@Wk+bk cols 0..127

__device__ __nv_bfloat16 g_qh[ROWS * QKC], g_ql[ROWS * QKC]; // quantum(qproj)
__device__ __nv_bfloat16 g_kh[ROWS * QKC], g_kl[ROWS * QKC]; // quantum(kproj)
__device__ __nv_bfloat16 g_vh[ROWS * QKC], g_vl[ROWS * QKC]; // v proj cols 0..127
__device__ __nv_bfloat16 g_aoh[ROWS * QKC], g_aol[ROWS * QKC]; // attn out h0,1

__device__ __nv_bfloat16 g_xh[ROWS * EMB], g_xl[ROWS * EMB];   // x split
__device__ __nv_bfloat16 g_wqh[EMB * EMB], g_wql[EMB * EMB];   // W^T splits
__device__ __nv_bfloat16 g_wkh[EMB * EMB], g_wkl[EMB * EMB];
__device__ __nv_bfloat16 g_wvh[EMB * EMB], g_wvl[EMB * EMB];
__device__ __nv_bfloat16 g_woh[EMB * EMB], g_wol[EMB * EMB];

__device__ float g_pm[BB * 8 * EMB];  // xmean partials
__device__ float g_xm[BB * EMB];      // per-batch column mean of x
__device__ float g_mv[BB * EMB];      // meanV (cols 128..1023 used)
__device__ float g_base[BB * EMB];    // per-batch output base (heads 2..15 + bo)

// ---------------- helpers ---------------------------------------------------
__device__ __forceinline__ uint32_t smem_u32(const void* p) {
    uint32_t a;
    asm("{ .reg .u64 t; cvta.to.shared.u64 t, %1; cvt.u32.u64 %0, t; }"
        : "=r"(a) : "l"(p));
    return a;
}

__device__ __forceinline__ void ldsm4(uint32_t* r, uint32_t addr) {
    asm volatile("ldmatrix.sync.aligned.m8n8.x4.shared.b16 {%0,%1,%2,%3}, [%4];"
                 : "=r"(r[0]), "=r"(r[1]), "=r"(r[2]), "=r"(r[3]) : "r"(addr));
}

__device__ __forceinline__ void ldsm4t(uint32_t* r, uint32_t addr) {
    asm volatile(
        "ldmatrix.sync.aligned.m8n8.x4.trans.shared.b16 {%0,%1,%2,%3}, [%4];"
        : "=r"(r[0]), "=r"(r[1]), "=r"(r[2]), "=r"(r[3]) : "r"(addr));
}

__device__ __forceinline__ void mma_bf16(float* d, const uint32_t* a,
                                         uint32_t b0, uint32_t b1) {
    asm("mma.sync.aligned.m16n8k16.row.col.f32.bf16.bf16.f32 "
        "{%0,%1,%2,%3}, {%4,%5,%6,%7}, {%8,%9}, {%0,%1,%2,%3};"
        : "+f"(d[0]), "+f"(d[1]), "+f"(d[2]), "+f"(d[3])
        : "r"(a[0]), "r"(a[1]), "r"(a[2]), "r"(a[3]), "r"(b0), "r"(b1));
}

__device__ __forceinline__ void mma_bf16_4(float* d, uint32_t a0, uint32_t a1,
                                           uint32_t a2, uint32_t a3,
                                           uint32_t b0, uint32_t b1) {
    asm("mma.sync.aligned.m16n8k16.row.col.f32.bf16.bf16.f32 "
        "{%0,%1,%2,%3}, {%4,%5,%6,%7}, {%8,%9}, {%0,%1,%2,%3};"
        : "+f"(d[0]), "+f"(d[1]), "+f"(d[2]), "+f"(d[3])
        : "r"(a0), "r"(a1), "r"(a2), "r"(a3), "r"(b0), "r"(b1));
}

__device__ __forceinline__ void cp16(uint32_t dst, const void* src) {
    asm volatile("cp.async.cg.shared.global [%0], [%1], 16;"
                 :: "r"(dst), "l"(src) : "memory");
}
__device__ __forceinline__ void cp_commit() {
    asm volatile("cp.async.commit_group;" ::: "memory");
}
__device__ __forceinline__ void cp_wait0() {
    asm volatile("cp.async.wait_group 0;" ::: "memory");
}
__device__ __forceinline__ void cp_wait1() {
    asm volatile("cp.async.wait_group 1;" ::: "memory");
}

__device__ __forceinline__ uint32_t packbf2(float a, float b) {
    __nv_bfloat162 t = __halves2bfloat162(__float2bfloat16(a), __float2bfloat16(b));
    return *(uint32_t*)&t;
}

// ---------------------------------------------------------------------------
// split fp32 -> bf16 hi/lo
// ---------------------------------------------------------------------------
__global__ __launch_bounds__(256) void split_bf16(
    const float* __restrict__ src,
    __nv_bfloat16* __restrict__ hi, __nv_bfloat16* __restrict__ lo, int n4)
{
    int i = blockIdx.x * blockDim.x + threadIdx.x;
    if (i >= n4) return;
    float4 v = ((const float4*)src)[i];
    __nv_bfloat16 h0 = __float2bfloat16(v.x), h1 = __float2bfloat16(v.y);
    __nv_bfloat16 h2 = __float2bfloat16(v.z), h3 = __float2bfloat16(v.w);
    __nv_bfloat16 l0 = __float2bfloat16(v.x - __bfloat162float(h0));
    __nv_bfloat16 l1 = __float2bfloat16(v.y - __bfloat162float(h1));
    __nv_bfloat16 l2 = __float2bfloat16(v.z - __bfloat162float(h2));
    __nv_bfloat16 l3 = __float2bfloat16(v.w - __bfloat162float(h3));
    __nv_bfloat162* hp = (__nv_bfloat162*)hi;
    __nv_bfloat162* lp = (__nv_bfloat162*)lo;
    hp[i * 2 + 0] = __halves2bfloat162(h0, h1);
    hp[i * 2 + 1] = __halves2bfloat162(h2, h3);
    lp[i * 2 + 0] = __halves2bfloat162(l0, l1);
    lp[i * 2 + 1] = __halves2bfloat162(l2, l3);
}

// ---------------------------------------------------------------------------
// transpose + split: Wt[n][k] = W[k][n] as bf16 hi/lo
// ---------------------------------------------------------------------------
__global__ __launch_bounds__(256) void tsplit_bf16(
    const float* __restrict__ W,
    __nv_bfloat16* __restrict__ th, __nv_bfloat16* __restrict__ tl)
{
    __shared__ float s[32][33];
    int tx = threadIdx.x, ty = threadIdx.y; // (32, 8)
    int n0 = blockIdx.x * 32, k0 = blockIdx.y * 32;
#pragma unroll
    for (int j = 0; j < 4; j++)
        s[ty + 8 * j][tx] = W[(size_t)(k0 + ty + 8 * j) * EMB + n0 + tx];
    __syncthreads();
#pragma unroll
    for (int j = 0; j < 4; j++) {
        int n = n0 + ty + 8 * j, k = k0 + tx;
        float v = s[tx][ty + 8 * j];
        __nv_bfloat16 h = __float2bfloat16(v);
        th[(size_t)n * EMB + k] = h;
        tl[(size_t)n * EMB + k] = __float2bfloat16(v - __bfloat162float(h));
    }
}

// ---------------------------------------------------------------------------
// GEMM core: cp.async 3-stage pipeline, one barrier per K-chunk.
// ---------------------------------------------------------------------------
#define SROW 40
#define TILE_B (128 * SROW * 2) /* 10240 */
#define STAGE_B (4 * TILE_B)    /* 40960 */
#define NSTAGE 3
#define GSMEM_TOTAL (NSTAGE * STAGE_B) /* 122880 */

struct GemmCore {
    uint32_t sb;
    int tid;
    uint32_t a_off, b_off;
    const __nv_bfloat16* gsrc[4];
    int gstr[4];
    float acc[4][4][4];

    __device__ __forceinline__ void init(char* smem, int tid_, int wid, int L,
                                         const __nv_bfloat16* ah,
                                         const __nv_bfloat16* al, int astr,
                                         const __nv_bfloat16* bh,
                                         const __nv_bfloat16* bl, int bstr) {
        sb = smem_u32(smem);
        tid = tid_;
        const int warp_m = (wid >> 2) * 64;
        const int warp_n = (wid & 3) * 32;
        a_off = (uint32_t)(warp_m + (L & 15)) * 80 + (L >> 4) * 16;
        b_off = (uint32_t)(warp_n + (L >> 4) * 8 + (L & 7)) * 80 + ((L >> 3) & 1) * 16;
        gsrc[0] = ah; gsrc[1] = al; gsrc[2] = bh; gsrc[3] = bl;
        gstr[0] = astr; gstr[1] = astr; gstr[2] = bstr; gstr[3] = bstr;
#pragma unroll
        for (int mt = 0; mt < 4; mt++)
#pragma unroll
            for (int nt = 0; nt < 4; nt++)
#pragma unroll
                for (int j = 0; j < 4; j++) acc[mt][nt][j] = 0.f;
    }

    __device__ __forceinline__ void issue(int kc, int stg) {
        const int k0 = kc * 32;
        const uint32_t stbase = sb + stg * STAGE_B;
#pragma unroll
        for (int u = 0; u < 8; ++u) {
            const int t = u >> 1;
            const int rem = tid + (u & 1) * 256;
            const int r = rem >> 2, c = rem & 3;
            cp16(stbase + t * TILE_B + (uint32_t)r * 80 + c * 16,
                 gsrc[t] + (size_t)r * gstr[t] + k0 + c * 8);
        }
        cp_commit();
    }

    template <int NC>
    __device__ __forceinline__ void run() {
        issue(0, 0);
        issue(1, 1);
        for (int kc = 0; kc < NC; ++kc) {
            if (kc + 2 < NC) cp_wait1(); else cp_wait0();
            __syncthreads();
            if (kc + 2 < NC) issue(kc + 2, (kc + 2) % NSTAGE);

            const uint32_t st = sb + (kc % NSTAGE) * STAGE_B;
#pragma unroll
            for (int ks = 0; ks < 2; ++ks) {
                uint32_t afh[4][4], afl[4][4], bfh[2][4], bfl[2][4];
#pragma unroll
                for (int mt = 0; mt < 4; mt++) {
                    uint32_t ad = st + a_off + mt * (16 * 80) + ks * 32;
                    ldsm4(afh[mt], ad);
                    ldsm4(afl[mt], ad + TILE_B);
                }
#pragma unroll
                for (int np = 0; np < 2; np++) {
                    uint32_t bd = st + 2 * TILE_B + b_off + np * (16 * 80) + ks * 32;
                    ldsm4(bfh[np], bd);
                    ldsm4(bfl[np], bd + TILE_B);
                }
#pragma unroll
                for (int mt = 0; mt < 4; mt++)
#pragma unroll
                    for (int np = 0; np < 2; np++) {
                        mma_bf16(acc[mt][np * 2 + 0], afh[mt], bfh[np][0], bfh[np][1]);
                        mma_bf16(acc[mt][np * 2 + 1], afh[mt], bfh[np][2], bfh[np][3]);
                    }
#pragma unroll
                for (int mt = 0; mt < 4; mt++)
#pragma unroll
                    for (int np = 0; np < 2; np++) {
                        mma_bf16(acc[mt][np * 2 + 0], afh[mt], bfl[np][0], bfl[np][1]);
                        mma_bf16(acc[mt][np * 2 + 1], afh[mt], bfl[np][2], bfl[np][3]);
                    }
#pragma unroll
                for (int mt = 0; mt < 4; mt++)
#pragma unroll
                    for (int np = 0; np < 2; np++) {
                        mma_bf16(acc[mt][np * 2 + 0], afl[mt], bfh[np][0], bfh[np][1]);
                        mma_bf16(acc[mt][np * 2 + 1], afl[mt], bfh[np][2], bfh[np][3]);
                    }
            }
        }
    }
};

// ---------------------------------------------------------------------------
// Fused projections (cols 0..127 only): grid (3, 64). bx: 0=q, 1=k, 2=v.
// q,k -> fp32 compact; v -> bf16 hi/lo compact (stride QKC).
// ---------------------------------------------------------------------------
__global__ __launch_bounds__(256) void gemm_qkv(
    const __nv_bfloat16* __restrict__ Xh, const __nv_bfloat16* __restrict__ Xl,
    const __nv_bfloat16* __restrict__ Wqh, const __nv_bfloat16* __restrict__ Wql,
    const __nv_bfloat16* __restrict__ Wkh, const __nv_bfloat16* __restrict__ Wkl,
    const __nv_bfloat16* __restrict__ Wvh, const __nv_bfloat16* __restrict__ Wvl,
    const float* __restrict__ bq, const float* __restrict__ bk,
    const float* __restrict__ bv,
    float* __restrict__ Qp, float* __restrict__ Kp,
    __nv_bfloat16* __restrict__ Vh, __nv_bfloat16* __restrict__ Vl)
{
    extern __shared__ char smem[];
    const int tid = threadIdx.x, wid = tid >> 5, L = tid & 31;
    const int wsel = blockIdx.x, by = blockIdx.y;

    const __nv_bfloat16* Bh = (wsel == 0) ? Wqh : (wsel == 1) ? Wkh : Wvh;
    const __nv_bfloat16* Bl = (wsel == 0) ? Wql : (wsel == 1) ? Wkl : Wvl;
    const float* bias = (wsel == 0) ? bq : (wsel == 1) ? bk : bv;

    GemmCore g;
    g.init(smem, tid, wid, L,
           Xh + (size_t)(by * 128) * EMB, Xl + (size_t)(by * 128) * EMB, EMB,
           Bh, Bl, EMB);
    g.run<EMB / 32>();

    const int warp_m = ((wid >> 2)) * 64, warp_n = (wid & 3) * 32;
    const int qr = L >> 2, qc = (L & 3) * 2;
#pragma unroll
    for (int mt = 0; mt < 4; mt++) {
#pragma unroll
        for (int nt = 0; nt < 4; nt++) {
            int col = warp_n + nt * 8 + qc;
            float b0 = bias[col], b1 = bias[col + 1];
            int r0 = by * 128 + warp_m + mt * 16 + qr;
            float v00 = g.acc[mt][nt][0] + b0, v01 = g.acc[mt][nt][1] + b1;
            float v10 = g.acc[mt][nt][2] + b0, v11 = g.acc[mt][nt][3] + b1;
            if (wsel < 2) {
                float* dst = (wsel == 0) ? Qp : Kp;
                *(float2*)&dst[(size_t)r0 * QKC + col] = make_float2(v00, v01);
                *(float2*)&dst[(size_t)(r0 + 8) * QKC + col] = make_float2(v10, v11);
            } else {
                float r00 = v00 - __bfloat162float(__float2bfloat16(v00));
                float r01 = v01 - __bfloat162float(__float2bfloat16(v01));
                float r10 = v10 - __bfloat162float(__float2bfloat16(v10));
                float r11 = v11 - __bfloat162float(__float2bfloat16(v11));
                *(uint32_t*)&Vh[(size_t)r0 * QKC + col] = packbf2(v00, v01);
                *(uint32_t*)&Vh[(size_t)(r0 + 8) * QKC + col] = packbf2(v10, v11);
                *(uint32_t*)&Vl[(size_t)r0 * QKC + col] = packbf2(r00, r01);
                *(uint32_t*)&Vl[(size_t)(r0 + 8) * QKC + col] = packbf2(r10, r11);
            }
        }
    }
}

// ---------------------------------------------------------------------------
// quantum: cumprod(cos) over 128 dims, warp per row. Fused q+k.
// ---------------------------------------------------------------------------
__global__ __launch_bounds__(256) void quantum_scan128(
    const float* __restrict__ inq, const float* __restrict__ ink,
    __nv_bfloat16* __restrict__ qh, __nv_bfloat16* __restrict__ ql,
    __nv_bfloat16* __restrict__ kh, __nv_bfloat16* __restrict__ kl)
{
    int gw = blockIdx.x * 8 + (threadIdx.x >> 5);
    int lane = threadIdx.x & 31;
    int row = (gw < ROWS) ? gw : gw - ROWS;
    const float* in = (gw < ROWS) ? inq : ink;
    __nv_bfloat16* oh = (gw < ROWS) ? qh : kh;
    __nv_bfloat16* ol = (gw < ROWS) ? ql : kl;

    float4 v = ((const float4*)(in + (size_t)row * QKC))[lane];
    float c0 = cosf(v.x), c1 = cosf(v.y), c2 = cosf(v.z), c3 = cosf(v.w);
    float p0 = c0, p1 = p0 * c1, p2 = p1 * c2, p3 = p2 * c3;

    float t = p3;
#pragma unroll
    for (int off = 1; off < 32; off <<= 1) {
        float o = __shfl_up_sync(0xffffffffu, t, off);
        if (lane >= off) t *= o;
    }
    float pref = __shfl_up_sync(0xffffffffu, t, 1);
    if (lane == 0) pref = 1.f;

    float f0 = pref * p0, f1 = pref * p1, f2 = pref * p2, f3 = pref * p3;
    uint32_t* hp = (uint32_t*)(oh + (size_t)row * QKC);
    uint32_t* lp = (uint32_t*)(ol + (size_t)row * QKC);
    hp[lane * 2 + 0] = packbf2(f0, f1);
    hp[lane * 2 + 1] = packbf2(f2, f3);
    float r0 = f0 - __bfloat162float(__float2bfloat16(f0));
    float r1 = f1 - __bfloat162float(__float2bfloat16(f1));
    float r2 = f2 - __bfloat162float(__float2bfloat16(f2));
    float r3 = f3 - __bfloat162float(__float2bfloat16(f3));
    lp[lane * 2 + 0] = packbf2(r0, r1);
    lp[lane * 2 + 1] = packbf2(r2, r3);
}

// ---------------------------------------------------------------------------
// Tensor-core flash attention (heads 0,1). All tensors compact stride QKC.
// ---------------------------------------------------------------------------
#define FSTRIDE 144
#define FQ_B (128 * FSTRIDE)
#define FKV_B (64 * FSTRIDE)
#define FSTAGE_B (4 * FKV_B)
#define FSMEM_TOTAL (2 * FQ_B + 2 * FSTAGE_B) /* 110592 */

__global__ __launch_bounds__(256) void flash_tc(
    const __nv_bfloat16* __restrict__ Qh_g, const __nv_bfloat16* __restrict__ Ql_g,
    const __nv_bfloat16* __restrict__ Kh_g, const __nv_bfloat16* __restrict__ Kl_g,
    const __nv_bfloat16* __restrict__ Vh_g, const __nv_bfloat16* __restrict__ Vl_g,
    __nv_bfloat16* __restrict__ Oh, __nv_bfloat16* __restrict__ Ol)
{
    extern __shared__ char smem[];
    const int tid = threadIdx.x, wid = tid >> 5, L = tid & 31;
    const int bh = blockIdx.y;
    const int b = bh >> 1, h = bh & 1;
    const int q0 = blockIdx.x * 128;
    const size_t rb = (size_t)b * TT;
    const int cb = h * HD;
    const uint32_t sb = smem_u32(smem);

#pragma unroll
    for (int u = 0; u < 4; ++u) {
        int idx = tid + u * 256;
        int r = idx >> 3, c = idx & 7;
        const size_t go = (rb + q0 + r) * QKC + cb + c * 8;
        *(uint4*)(smem + r * FSTRIDE + c * 16) = *(const uint4*)(Qh_g + go);
        *(uint4*)(smem + FQ_B + r * FSTRIDE + c * 16) = *(const uint4*)(Ql_g + go);
    }

    const __nv_bfloat16* kvsrc[4] = {Kh_g, Kl_g, Vh_g, Vl_g};
    auto issue_kv = [&](int key0, int stg) {
#pragma unroll
        for (int u = 0; u < 8; ++u) {
            int idx = tid + u * 256;
            int t = idx >> 9, rem = idx & 511;
            int r = rem >> 3, c = rem & 7;
            uint32_t dst = sb + 2 * FQ_B + stg * FSTAGE_B + t * FKV_B +
                           r * FSTRIDE + c * 16;
            cp16(dst, kvsrc[t] + (rb + key0 + r) * (size_t)QKC + cb + c * 8);
        }
        cp_commit();
    };

    issue_kv(0, 0);
    __syncthreads();

    const uint32_t qa_off = (uint32_t)(wid * 16 + (L & 15)) * FSTRIDE + (L >> 4) * 16;
    uint32_t qfh[4][4], qfl[4][4];
#pragma unroll
    for (int kk = 0; kk < 4; ++kk) {
        ldsm4(qfh[kk], sb + qa_off + kk * 32);
        ldsm4(qfl[kk], sb + FQ_B + qa_off + kk * 32);
    }

    const uint32_t kb_off =
        (uint32_t)((L >> 4) * 8 + (L & 7)) * FSTRIDE + ((L >> 3) & 1) * 16;
    const uint32_t vt_key = ((L >> 3) & 1) * 8 + (L & 7);
    const uint32_t vt_d = (L >> 4) * 8;

    float mA = -INFINITY, mB = -INFINITY, lA = 0.f, lB = 0.f;
    float oacc[8][4];
#pragma unroll
    for (int nt = 0; nt < 8; nt++)
#pragma unroll
        for (int j = 0; j < 4; j++) oacc[nt][j] = 0.f;

    const int NT = TT / 64;
    for (int kt = 0; kt < NT; ++kt) {
        const int cur = kt & 1;
        cp_wait0();
        __syncthreads();
        if (kt + 1 < NT) issue_kv((kt + 1) * 64, cur ^ 1);

        const uint32_t Kh_s = sb + 2 * FQ_B + cur * FSTAGE_B;
        const uint32_t Kl_s = Kh_s + FKV_B;
        const uint32_t Vh_s = Kh_s + 2 * FKV_B;
        const uint32_t Vl_s = Kh_s + 3 * FKV_B;

        float sacc[8][4];
#pragma unroll
        for (int nt = 0; nt < 8; nt++)
#pragma unroll
            for (int j = 0; j < 4; j++) sacc[nt][j] = 0.f;

#pragma unroll
        for (int kk = 0; kk < 4; ++kk) {
            uint32_t kh[4][4], kl[4][4];
#pragma unroll
            for (int np = 0; np < 4; np++) {
                uint32_t bd = kb_off + np * (16 * FSTRIDE) + kk * 32;
                ldsm4(kh[np], Kh_s + bd);
                ldsm4(kl[np], Kl_s + bd);
            }
#pragma unroll
            for (int np = 0; np < 4; np++) {
                mma_bf16(sacc[np * 2 + 0], qfh[kk], kh[np][0], kh[np][1]);
                mma_bf16(sacc[np * 2 + 1], qfh[kk], kh[np][2], kh[np][3]);
            }
#pragma unroll
            for (int np = 0; np < 4; np++) {
                mma_bf16(sacc[np * 2 + 0], qfh[kk], kl[np][0], kl[np][1]);
                mma_bf16(sacc[np * 2 + 1], qfh[kk], kl[np][2], kl[np][3]);
            }
#pragma unroll
            for (int np = 0; np < 4; np++) {
                mma_bf16(sacc[np * 2 + 0], qfl[kk], kh[np][0], kh[np][1]);
                mma_bf16(sacc[np * 2 + 1], qfl[kk], kh[np][2], kh[np][3]);
            }
        }

        float mxA = -INFINITY, mxB = -INFINITY;
#pragma unroll
        for (int nt = 0; nt < 8; nt++) {
            sacc[nt][0] *= 0.125f; sacc[nt][1] *= 0.125f;
            sacc[nt][2] *= 0.125f; sacc[nt][3] *= 0.125f;
            mxA = fmaxf(mxA, fmaxf(sacc[nt][0], sacc[nt][1]));
            mxB = fmaxf(mxB, fmaxf(sacc[nt][2], sacc[nt][3]));
        }
        mxA = fmaxf(mxA, __shfl_xor_sync(0xffffffffu, mxA, 1));
        mxA = fmaxf(mxA, __shfl_xor_sync(0xffffffffu, mxA, 2));
        mxB = fmaxf(mxB, __shfl_xor_sync(0xffffffffu, mxB, 1));
        mxB = fmaxf(mxB, __shfl_xor_sync(0xffffffffu, mxB, 2));

        float mnA = fmaxf(mA, mxA), mnB = fmaxf(mB, mxB);
        float corrA = __expf(mA - mnA), corrB = __expf(mB - mnB);

        uint32_t ph01[8], ph23[8], pl01[8], pl23[8];
        float sumA = 0.f, sumB = 0.f;
#pragma unroll
        for (int nt = 0; nt < 8; nt++) {
            float p0 = __expf(sacc[nt][0] - mnA);
            float p1 = __expf(sacc[nt][1] - mnA);
            float p2 = __expf(sacc[nt][2] - mnB);
            float p3 = __expf(sacc[nt][3] - mnB);
            sumA += p0 + p1;
            sumB += p2 + p3;
            ph01[nt] = packbf2(p0, p1);
            ph23[nt] = packbf2(p2, p3);
            float r0 = p0 - __bfloat162float(__float2bfloat16(p0));
            float r1 = p1 - __bfloat162float(__float2bfloat16(p1));
            float r2 = p2 - __bfloat162float(__float2bfloat16(p2));
            float r3 = p3 - __bfloat162float(__float2bfloat16(p3));
            pl01[nt] = packbf2(r0, r1);
            pl23[nt] = packbf2(r2, r3);
        }
        sumA += __shfl_xor_sync(0xffffffffu, sumA, 1);
        sumA += __shfl_xor_sync(0xffffffffu, sumA, 2);
        sumB += __shfl_xor_sync(0xffffffffu, sumB, 1);
        sumB += __shfl_xor_sync(0xffffffffu, sumB, 2);

        lA = lA * corrA + sumA; mA = mnA;
        lB = lB * corrB + sumB; mB = mnB;
#pragma unroll
        for (int nt = 0; nt < 8; nt++) {
            oacc[nt][0] *= corrA; oacc[nt][1] *= corrA;
            oacc[nt][2] *= corrB; oacc[nt][3] *= corrB;
        }

#pragma unroll
        for (int kk = 0; kk < 4; ++kk) {
            uint32_t vkey = (vt_key + kk * 16) * FSTRIDE;
#pragma unroll
            for (int pr = 0; pr < 2; ++pr) {
                uint32_t vh[2][4], vl[2][4];
#pragma unroll
                for (int j = 0; j < 2; ++j) {
                    uint32_t va = vkey + (vt_d + (pr * 2 + j) * 16) * 2;
                    ldsm4t(vh[j], Vh_s + va);
                    ldsm4t(vl[j], Vl_s + va);
                }
#pragma unroll
                for (int j = 0; j < 2; ++j) {
                    int p = pr * 2 + j;
                    mma_bf16_4(oacc[2 * p + 0], ph01[2 * kk], ph23[2 * kk],
                               ph01[2 * kk + 1], ph23[2 * kk + 1], vh[j][0], vh[j][1]);
                    mma_bf16_4(oacc[2 * p + 1], ph01[2 * kk], ph23[2 * kk],
                               ph01[2 * kk + 1], ph23[2 * kk + 1], vh[j][2], vh[j][3]);
                }
#pragma unroll
                for (int j = 0; j < 2; ++j) {
                    int p = pr * 2 + j;
                    mma_bf16_4(oacc[2 * p + 0], ph01[2 * kk], ph23[2 * kk],
                               ph01[2 * kk + 1], ph23[2 * kk + 1], vl[j][0], vl[j][1]);
                    mma_bf16_4(oacc[2 * p + 1], ph01[2 * kk], ph23[2 * kk],
                               ph01[2 * kk + 1], ph23[2 * kk + 1], vl[j][2], vl[j][3]);
                }
#pragma unroll
                for (int j = 0; j < 2; ++j) {
                    int p = pr * 2 + j;
                    mma_bf16_4(oacc[2 * p + 0], pl01[2 * kk], pl23[2 * kk],
                               pl01[2 * kk + 1], pl23[2 * kk + 1], vh[j][0], vh[j][1]);
                    mma_bf16_4(oacc[2 * p + 1], pl01[2 * kk], pl23[2 * kk],
                               pl01[2 * kk + 1], pl23[2 * kk + 1], vh[j][2], vh[j][3]);
                }
            }
        }
    }

    float invA = 1.0f / lA, invB = 1.0f / lB;
    const size_t rowA = (rb + q0 + wid * 16 + (L >> 2)) * QKC;
    const size_t rowB = rowA + 8 * QKC;
#pragma unroll
    for (int nt = 0; nt < 8; nt++) {
        int col = cb + nt * 8 + (L & 3) * 2;
        float v0 = oacc[nt][0] * invA, v1 = oacc[nt][1] * invA;
        float v2 = oacc[nt][2] * invB, v3 = oacc[nt][3] * invB;
        *(uint32_t*)&Oh[rowA + col] = packbf2(v0, v1);
        *(uint32_t*)&Oh[rowB + col] = packbf2(v2, v3);
        float r0 = v0 - __bfloat162float(__float2bfloat16(v0));
        float r1 = v1 - __bfloat162float(__float2bfloat16(v1));
        float r2 = v2 - __bfloat162float(__float2bfloat16(v2));
        float r3 = v3 - __bfloat162float(__float2bfloat16(v3));
        *(uint32_t*)&Ol[rowA + col] = packbf2(r0, r1);
        *(uint32_t*)&Ol[rowB + col] = packbf2(r2, r3);
    }
}

// ---------------------------------------------------------------------------
// xmean: column means of x per batch. Partials over 256-row chunks.
// ---------------------------------------------------------------------------
__global__ __launch_bounds__(128) void xmean_part(const float* __restrict__ x,
                                                  float* __restrict__ pm)
{
    int col = blockIdx.x * 128 + threadIdx.x;
    int b = blockIdx.y, chunk = blockIdx.z;
    int row0 = b * TT + chunk * 256;
    float s = 0.f;
    for (int r = 0; r < 256; ++r)
        s += x[(size_t)(row0 + r) * EMB + col];
    pm[((size_t)b * 8 + chunk) * EMB + col] = s;
}

__global__ __launch_bounds__(128) void xmean_reduce(const float* __restrict__ pm,
                                                    float* __restrict__ xm)
{
    int col = blockIdx.x * 128 + threadIdx.x;
    int b = blockIdx.y;
    float s = 0.f;
#pragma unroll
    for (int c = 0; c < 8; ++c) s += pm[((size_t)b * 8 + c) * EMB + col];
    xm[(size_t)b * EMB + col] = s * (1.f / TT);
}

// meanV[b][c] = bv[c] + sum_k xm[b][k] * Wv[k][c], c in [128, 1024). Pure fp32.
__global__ __launch_bounds__(128) void meanv_gemv(
    const float* __restrict__ xm, const float* __restrict__ Wv,
    const float* __restrict__ bv, float* __restrict__ mv)
{
    int c = 128 + blockIdx.x * 128 + threadIdx.x;
    int b = blockIdx.y;
    const float* m = xm + (size_t)b * EMB;
    float acc = bv[c];
    for (int k = 0; k < EMB; ++k)
        acc = fmaf(m[k], Wv[(size_t)k * EMB + c], acc);
    mv[(size_t)b * EMB + c] = acc;
}

// base[b][n] = bo[n] + sum_{c=128..1023} mv[b][c] * Wo[c][n]. Pure fp32.
__global__ __launch_bounds__(256) void base_out(
    const float* __restrict__ mv, const float* __restrict__ Wo,
    const float* __restrict__ bo, float* __restrict__ base)
{
    int n = blockIdx.x * 256 + threadIdx.x;
    int b = blockIdx.y;
    const float* m = mv + (size_t)b * EMB;
    float acc = bo[n];
    for (int c = 128; c < EMB; ++c)
        acc = fmaf(m[c], Wo[(size_t)c * EMB + n], acc);
    base[(size_t)b * EMB + n] = acc;
}

// ---------------------------------------------------------------------------
// Output projection, K=128 (heads 0,1 contribution) + per-batch base.
// ---------------------------------------------------------------------------
__global__ __launch_bounds__(256) void gemm_out128(
    const __nv_bfloat16* __restrict__ Ah, const __nv_bfloat16* __restrict__ Al,
    const __nv_bfloat16* __restrict__ Bh, const __nv_bfloat16* __restrict__ Bl,
    const float* __restrict__ base, float* __restrict__ C)
{
    extern __shared__ char smem[];
    const int tid = threadIdx.x, wid = tid >> 5, L = tid & 31;
    const int bx = blockIdx.x, by = blockIdx.y;

    GemmCore g;
    g.init(smem, tid, wid, L,
           Ah + (size_t)(by * 128) * QKC, Al + (size_t)(by * 128) * QKC, QKC,
           Bh + (size_t)(bx * 128) * EMB, Bl + (size_t)(bx * 128) * EMB, EMB);
    g.run<QKC / 32>();

    const int b = by >> 4; // 16 row-blocks per batch
    const int warp_m = (wid >> 2) * 64, warp_n = (wid & 3) * 32;
    const int qr = L >> 2, qc = (L & 3) * 2;
#pragma unroll
    for (int mt = 0; mt < 4; mt++) {
#pragma unroll
        for (int nt = 0; nt < 4; nt++) {
            int col = bx * 128 + warp_n + nt * 8 + qc;
            float b0 = base[(size_t)b * EMB + col];
            float b1 = base[(size_t)b * EMB + col + 1];
            int r0 = by * 128 + warp_m + mt * 16 + qr;
            *(float2*)&C[(size_t)r0 * EMB + col] =
                make_float2(g.acc[mt][nt][0] + b0, g.acc[mt][nt][1] + b1);
            *(float2*)&C[(size_t)(r0 + 8) * EMB + col] =
                make_float2(g.acc[mt][nt][2] + b0, g.acc[mt][nt][3] + b1);
        }
    }
}

// ---------------------------------------------------------------------------
extern "C" void kernel_launch(void* const* d_in, const int* in_sizes, int n_in,
                              void* d_out, int out_size)
{
    const float* x  = (const float*)d_in[0];
    const float* Wq = (const float*)d_in[1];
    const float* bq = (const float*)d_in[2];
    const float* Wk = (const float*)d_in[3];
    const float* bk = (const float*)d_in[4];
    const float* Wv = (const float*)d_in[5];
    const float* bv = (const float*)d_in[6];
    const float* Wo = (const float*)d_in[7];
    const float* bo = (const float*)d_in[8];
    float* out = (float*)d_out;

    float *qp, *kp, *pm, *xm, *mv, *base;
    cudaGetSymbolAddress((void**)&qp, g_qp);
    cudaGetSymbolAddress((void**)&kp, g_kp);
    cudaGetSymbolAddress((void**)&pm, g_pm);
    cudaGetSymbolAddress((void**)&xm, g_xm);
    cudaGetSymbolAddress((void**)&mv, g_mv);
    cudaGetSymbolAddress((void**)&base, g_base);

    __nv_bfloat16 *qh, *ql, *kh, *kl, *vh, *vl, *aoh, *aol, *xh, *xl;
    __nv_bfloat16 *wqh, *wql, *wkh, *wkl, *wvh, *wvl, *woh, *wol;
    cudaGetSymbolAddress((void**)&qh, g_qh);
    cudaGetSymbolAddress((void**)&ql, g_ql);
    cudaGetSymbolAddress((void**)&kh, g_kh);
    cudaGetSymbolAddress((void**)&kl, g_kl);
    cudaGetSymbolAddress((void**)&vh, g_vh);
    cudaGetSymbolAddress((void**)&vl, g_vl);
    cudaGetSymbolAddress((void**)&aoh, g_aoh);
    cudaGetSymbolAddress((void**)&aol, g_aol);
    cudaGetSymbolAddress((void**)&xh, g_xh);
    cudaGetSymbolAddress((void**)&xl, g_xl);
    cudaGetSymbolAddress((void**)&wqh, g_wqh);
    cudaGetSymbolAddress((void**)&wql, g_wql);
    cudaGetSymbolAddress((void**)&wkh, g_wkh);
    cudaGetSymbolAddress((void**)&wkl, g_wkl);
    cudaGetSymbolAddress((void**)&wvh, g_wvh);
    cudaGetSymbolAddress((void**)&wvl, g_wvl);
    cudaGetSymbolAddress((void**)&woh, g_woh);
    cudaGetSymbolAddress((void**)&wol, g_wol);

    cudaFuncSetAttribute(gemm_qkv, cudaFuncAttributeMaxDynamicSharedMemorySize,
                         GSMEM_TOTAL);
    cudaFuncSetAttribute(gemm_out128, cudaFuncAttributeMaxDynamicSharedMemorySize,
                         GSMEM_TOTAL);
    cudaFuncSetAttribute(flash_tc, cudaFuncAttributeMaxDynamicSharedMemorySize,
                         FSMEM_TOTAL);

    const int n4 = ROWS * EMB / 4;
    split_bf16<<<(n4 + 255) / 256, 256>>>(x, xh, xl, n4);

    dim3 tb(32, 8);
    tsplit_bf16<<<dim3(4, 32), tb>>>(Wq, wqh, wql);   // rows n<128 only
    tsplit_bf16<<<dim3(4, 32), tb>>>(Wk, wkh, wkl);   // rows n<128 only
    tsplit_bf16<<<dim3(4, 32), tb>>>(Wv, wvh, wvl);   // rows n<128 only
    tsplit_bf16<<<dim3(32, 4), tb>>>(Wo, woh, wol);   // k<128 only

    // heads 2..15 closed form: meanV from xmean (fp32 exact path)
    xmean_part<<<dim3(8, BB, 8), 128>>>(x, pm);
    xmean_reduce<<<dim3(8, BB), 128>>>(pm, xm);
    meanv_gemv<<<dim3(7, BB), 128>>>(xm, Wv, bv, mv);
    base_out<<<dim3(4, BB), 256>>>(mv, Wo, bo, base);

    gemm_qkv<<<dim3(3, ROWS / 128), 256, GSMEM_TOTAL>>>(
        xh, xl, wqh, wql, wkh, wkl, wvh, wvl, bq, bk, bv, qp, kp, vh, vl);

    quantum_scan128<<<2 * ROWS / 8, 256>>>(qp, kp, qh, ql, kh, kl);

    // Role swap per reference: query = quantum(k-proj), key = quantum(q-proj)
    flash_tc<<<dim3(TT / 128, BB * 2), 256, FSMEM_TOTAL>>>(
        kh, kl, qh, ql, vh, vl, aoh, aol);

    gemm_out128<<<dim3(EMB / 128, ROWS / 128), 256, GSMEM_TOTAL>>>(
        aoh, aol, woh, wol, base, out);
}